// round 10
// baseline (speedup 1.0000x reference)
#include <cuda_runtime.h>

// transforms_blue: per-pixel BGR2GRAY + conditional channel boost, fp32 in/out.
// Layout [B=64, C=3, H=512, W=512]; channel plane = 512*512 = 262144 floats.
//
// sm_100 256-bit vector memory ops: each thread processes 8 consecutive floats
// per plane via ld/st.global.v8.f32 (32B lane stride == 32B access size, so
// every warp access is a contiguous 1KB run -> full coalescing), halving the
// LDG/STG instruction count vs the float4 version. Streaming (evict-first)
// hints on both zero-reuse streams.

#define PLANE   262144          // floats per channel plane (512*512)
#define PLANE8  (PLANE / 8)     // 32768 float8-groups per plane
#define BATCH_STRIDE (3 * PLANE)
#define NGRP    (64 * PLANE8)   // 2,097,152 groups (divides 128 exactly)
#define THREADS 128

struct f8 { float v[8]; };

__device__ __forceinline__ f8 ldg256_cs(const float* p) {
    f8 r;
    asm volatile(
        "ld.global.cs.v8.f32 {%0,%1,%2,%3,%4,%5,%6,%7}, [%8];"
        : "=f"(r.v[0]), "=f"(r.v[1]), "=f"(r.v[2]), "=f"(r.v[3]),
          "=f"(r.v[4]), "=f"(r.v[5]), "=f"(r.v[6]), "=f"(r.v[7])
        : "l"(p));
    return r;
}

__device__ __forceinline__ void stg256_cs(float* p, const f8& r) {
    asm volatile(
        "st.global.cs.v8.f32 [%0], {%1,%2,%3,%4,%5,%6,%7,%8};"
        :: "l"(p),
           "f"(r.v[0]), "f"(r.v[1]), "f"(r.v[2]), "f"(r.v[3]),
           "f"(r.v[4]), "f"(r.v[5]), "f"(r.v[6]), "f"(r.v[7])
        : "memory");
}

__device__ __forceinline__ float gray_of(float x0, float x1, float x2) {
    float u0 = floorf(x0 * 255.0f);
    float u1 = floorf(x1 * 255.0f);
    float u2 = floorf(x2 * 255.0f);
    return rintf(0.114f * u0 + 0.587f * u1 + 0.299f * u2);  // jnp.round = half-even
}

__global__ void __launch_bounds__(THREADS) transforms_blue_kernel(
    const float* __restrict__ in, float* __restrict__ out)
{
    unsigned g = blockIdx.x * THREADS + threadIdx.x;   // exact grid, no check

    unsigned b    = g >> 15;            // g / PLANE8
    unsigned off  = (g & 32767u) * 8;   // float offset within plane
    unsigned base = b * BATCH_STRIDE + off;

    // 3 independent, fully-coalesced, streaming 256-bit loads
    const f8 v0 = ldg256_cs(in + base);
    const f8 v1 = ldg256_cs(in + base + PLANE);
    const f8 v2 = ldg256_cs(in + base + 2 * PLANE);

    f8 o0, o1, o2;
    const float inv255 = 1.0f / 255.0f;

    #pragma unroll
    for (int i = 0; i < 8; i++) {
        float gy = gray_of(v0.v[i], v1.v[i], v2.v[i]);
        bool m = gy < 128.0f;
        o0.v[i] = (m ? gy + 60.0f : gy) * inv255;
        o1.v[i] = (m ? gy + 10.0f : gy) * inv255;
        o2.v[i] = gy * inv255;
    }

    stg256_cs(out + base,             o0);
    stg256_cs(out + base + PLANE,     o1);
    stg256_cs(out + base + 2 * PLANE, o2);
}

extern "C" void kernel_launch(void* const* d_in, const int* in_sizes, int n_in,
                              void* d_out, int out_size) {
    const float* in = (const float*)d_in[0];
    float* out = (float*)d_out;
    const int blocks = NGRP / THREADS;   // 16384, exact
    transforms_blue_kernel<<<blocks, THREADS>>>(in, out);
}

// round 11
// speedup vs baseline: 1.0215x; 1.0215x over previous
#include <cuda_runtime.h>

// transforms_blue: per-pixel BGR2GRAY + conditional channel boost, fp32 in/out.
// Layout [B=64, C=3, H=512, W=512]; channel plane = 512*512 = 262144 floats.
//
// FINAL converged kernel (10 rounds). HBM-bound at the achieved-DRAM ceiling
// (~6.2 TB/s, ~76% of spec) for this 3-read/3-write plane-interleaved stream.
// Verified-neutral: MLP 3->6, v8.f32 256-bit ops, all L2 hint combos, CTA
// 128/256, persistent grids. Regressions: strided groups (coalescing loss),
// under-occupancy. Logical traffic (403MB) irreducible; L2 absorbs ~15%.
//
// Shape: 128 thr/CTA, 1 float4-group/thread, fully coalesced LDG.128/STG.128,
// streaming (evict-first) hints on both zero-reuse streams, exact grid.

#define PLANE   262144          // floats per channel plane (512*512)
#define PLANE4  (PLANE / 4)     // 65536 float4 per plane
#define BATCH_STRIDE (3 * PLANE)
#define NPIX4   (64 * PLANE4)   // 4,194,304 float4 pixel-groups (divides 128)
#define THREADS 128

__device__ __forceinline__ float gray_of(float x0, float x1, float x2) {
    float u0 = floorf(x0 * 255.0f);
    float u1 = floorf(x1 * 255.0f);
    float u2 = floorf(x2 * 255.0f);
    return rintf(0.114f * u0 + 0.587f * u1 + 0.299f * u2);  // jnp.round = half-even
}

__device__ __forceinline__ void px(float a, float b, float c,
                                   float& r0, float& r1, float& r2) {
    const float inv255 = 1.0f / 255.0f;
    float gy = gray_of(a, b, c);
    bool m = gy < 128.0f;
    r0 = (m ? gy + 60.0f : gy) * inv255;
    r1 = (m ? gy + 10.0f : gy) * inv255;
    r2 = gy * inv255;
}

__global__ void __launch_bounds__(THREADS) transforms_blue_kernel(
    const float* __restrict__ in, float* __restrict__ out)
{
    unsigned g = blockIdx.x * THREADS + threadIdx.x;   // exact grid, no check

    unsigned b    = g >> 16;            // g / PLANE4
    unsigned off  = (g & 65535u) * 4;   // float offset within plane
    unsigned base = b * BATCH_STRIDE + off;

    // 3 independent, fully-coalesced, streaming 128-bit loads
    const float4 v0 = __ldcs(reinterpret_cast<const float4*>(in + base));
    const float4 v1 = __ldcs(reinterpret_cast<const float4*>(in + base + PLANE));
    const float4 v2 = __ldcs(reinterpret_cast<const float4*>(in + base + 2 * PLANE));

    float4 o0, o1, o2;
    px(v0.x, v1.x, v2.x, o0.x, o1.x, o2.x);
    px(v0.y, v1.y, v2.y, o0.y, o1.y, o2.y);
    px(v0.z, v1.z, v2.z, o0.z, o1.z, o2.z);
    px(v0.w, v1.w, v2.w, o0.w, o1.w, o2.w);

    __stcs(reinterpret_cast<float4*>(out + base),             o0);
    __stcs(reinterpret_cast<float4*>(out + base + PLANE),     o1);
    __stcs(reinterpret_cast<float4*>(out + base + 2 * PLANE), o2);
}

extern "C" void kernel_launch(void* const* d_in, const int* in_sizes, int n_in,
                              void* d_out, int out_size) {
    const float* in = (const float*)d_in[0];
    float* out = (float*)d_out;
    const int blocks = NPIX4 / THREADS;   // 32768, exact
    transforms_blue_kernel<<<blocks, THREADS>>>(in, out);
}